// round 10
// baseline (speedup 1.0000x reference)
#include <cuda_runtime.h>
#include <cuda_fp16.h>
#include <cstdint>

#define EDIM   512
#define MROWS  32768
#define HDIM   1024
#define LN_EPS 1e-5f

// ---------------- mma.sync GEMM tiling ----------------
#define BM 128
#define BN 256
#define BK 64
#define NTHR 256

#define ROWB   144                   // 128B row + 16B pad: +4 banks/row, conflict-free ldmatrix
#define A_ROWS 128
#define B_ROWS 256
#define ARRB_A (A_ROWS * ROWB)       // 18432
#define ARRB_B (B_ROWS * ROWB)       // 36864
#define STAGEB (ARRB_A + ARRB_B)     // 55296
#define NSTAGE 3
#define DYN_SMEM (NSTAGE * STAGEB)   // 165888

#define MN (MROWS * EDIM)
#define MH (MROWS * HDIM)
#define WOFF_VO 0
#define WOFF_W1 262144
#define WOFF_W2 786432
#define WSTRIDE 1310720

// ---------------- device scratch ----------------
__device__ float   g_bvo[2 * EDIM];
__device__ __half  g_wh [2 * WSTRIDE];      // fp16 weights (B operands)
__device__ __half  g_xh [2 * MN];           // fp16 inputs
__device__ __half  g_x1h[2 * MN];           // fp16 x1 (GEMM operand)
__device__ float   g_x1f[2 * MN];           // fp32 x1 (LN2 residual)
__device__ __half  g_hh [2l * MH];          // fp16 relu(FFN up)
__device__ float   g_Y  [2 * MN];           // fp32 GEMM out scratch

// ---------------- PTX helpers ----------------
__device__ __forceinline__ uint32_t smem_u32(const void* p) {
    uint32_t a;
    asm("{ .reg .u64 t; cvta.to.shared.u64 t, %1; cvt.u32.u64 %0, t; }" : "=r"(a) : "l"(p));
    return a;
}
__device__ __forceinline__ void ldsm4(uint32_t* r, uint32_t addr) {
    asm volatile("ldmatrix.sync.aligned.x4.m8n8.shared.b16 {%0,%1,%2,%3}, [%4];"
                 : "=r"(r[0]), "=r"(r[1]), "=r"(r[2]), "=r"(r[3]) : "r"(addr));
}
__device__ __forceinline__ void mma_f16(float* c, const uint32_t* a, const uint32_t* b) {
    asm volatile(
        "mma.sync.aligned.m16n8k16.row.col.f32.f16.f16.f32 "
        "{%0,%1,%2,%3}, {%4,%5,%6,%7}, {%8,%9}, {%0,%1,%2,%3};"
        : "+f"(c[0]), "+f"(c[1]), "+f"(c[2]), "+f"(c[3])
        : "r"(a[0]), "r"(a[1]), "r"(a[2]), "r"(a[3]), "r"(b[0]), "r"(b[1]));
}
__device__ __forceinline__ void cp16(uint32_t dst, const void* src) {
    asm volatile("cp.async.cg.shared.global [%0], [%1], 16;" :: "r"(dst), "l"(src) : "memory");
}

// ---------------------------------------------------------------------------
struct GArgs {
    const __half *Ah, *Bh;
    const float* bias;
    float* Y;
    __half* Oh;
};

// GEMM: C[row0:BM, ncol0:BN] = A @ B^T (K-major fp16, fp32 accum).
// Warp grid 2(M) x 4(N); warp tile 64x64; acc[4][8][4].
// EPI 0: Y = acc + bias (fp32).  EPI 1: Oh = fp16(relu(acc + bias)).
template<int EPI>
__global__ __launch_bounds__(NTHR, 1)
void gemm_mma(GArgs ga0, GArgs ga1, int lda, int ldb, int K, int ldy, int ldo)
{
    extern __shared__ char smraw[];
    const uint32_t sb = smem_u32(smraw);
    const GArgs ga = blockIdx.z ? ga1 : ga0;

    const int t  = threadIdx.x;
    const int l  = t & 31;
    const int w  = t >> 5;
    const int wr = w >> 2;               // 0..1 (M half, 64 rows)
    const int wn = w & 3;                // 0..3 (N quarter, 64 cols)
    const int ncol0 = blockIdx.x * BN;   // N fastest -> A tile L2 reuse
    const int row0  = blockIdx.y * BM;

    // cp.async plan: 12 x 16B per thread per stage (4 A rows + 8 B rows, stride 32)
    const int crow = t >> 3;             // 0..31
    const int cc16 = (t & 7) * 16;
    const __half* pA = ga.Ah + (size_t)(row0 + crow) * lda + (t & 7) * 8;
    const __half* pB = ga.Bh + (size_t)(ncol0 + crow) * ldb + (t & 7) * 8;
    const uint32_t dbase = (uint32_t)crow * ROWB + cc16;

    float acc[4][8][4];
    #pragma unroll
    for (int mt = 0; mt < 4; mt++)
        #pragma unroll
        for (int nt = 0; nt < 8; nt++)
            #pragma unroll
            for (int e = 0; e < 4; e++) acc[mt][nt][e] = 0.f;

    const int nch = K / BK;

    auto fill = [&](int stage, int kt) {
        const uint32_t dst = sb + stage * STAGEB;
        #pragma unroll
        for (int j = 0; j < 4; j++)
            cp16(dst + dbase + (uint32_t)(j * 32) * ROWB, pA + (size_t)(j * 32) * lda + kt);
        #pragma unroll
        for (int j = 0; j < 8; j++)
            cp16(dst + ARRB_A + dbase + (uint32_t)(j * 32) * ROWB, pB + (size_t)(j * 32) * ldb + kt);
    };

    fill(0, 0);
    asm volatile("cp.async.commit_group;" ::: "memory");
    fill(1, BK);
    asm volatile("cp.async.commit_group;" ::: "memory");

    const uint32_t a_row  = (uint32_t)(wr * 64 + (l & 15)) * ROWB;
    const uint32_t a_chk  = (uint32_t)(l >> 4) << 4;
    const uint32_t b_row0 = (uint32_t)(wn * 64 + (l >> 4) * 8 + (l & 7)) * ROWB;
    const uint32_t b_chk  = (uint32_t)((l >> 3) & 1) << 4;

    int st_cur = 0, st_n2 = 2;
    for (int ch = 0; ch < nch; ch++) {
        asm volatile("cp.async.wait_group 1;" ::: "memory");
        __syncthreads();

        if (ch + 2 < nch) fill(st_n2, (ch + 2) * BK);
        asm volatile("cp.async.commit_group;" ::: "memory");

        const uint32_t sA = sb + st_cur * STAGEB;
        #pragma unroll
        for (int ks = 0; ks < 4; ks++) {
            const uint32_t koff = (uint32_t)ks * 32;   // 16 halves per k-step
            uint32_t b_h[4][4];
            #pragma unroll
            for (int p = 0; p < 4; p++)
                ldsm4(b_h[p], sA + ARRB_A + b_row0 + (uint32_t)(p * 16) * ROWB + koff + b_chk);
            uint32_t a[4][4];
            #pragma unroll
            for (int mt = 0; mt < 4; mt++)
                ldsm4(a[mt], sA + a_row + (uint32_t)(mt * 16) * ROWB + koff + a_chk);
            #pragma unroll
            for (int mt = 0; mt < 4; mt++)
                #pragma unroll
                for (int nt = 0; nt < 8; nt++)
                    mma_f16(acc[mt][nt], a[mt], &b_h[nt >> 1][(nt & 1) * 2]);
        }
        st_cur = (st_cur == 2) ? 0 : st_cur + 1;
        st_n2  = (st_n2  == 2) ? 0 : st_n2  + 1;
    }

    // ---------------- epilogue ----------------
    #pragma unroll
    for (int mt = 0; mt < 4; mt++) {
        #pragma unroll
        for (int nt = 0; nt < 8; nt++) {
            const int r_base = row0 + wr * 64 + mt * 16 + (l >> 2);
            const int gcol   = ncol0 + wn * 64 + nt * 8 + (l & 3) * 2;
            const float b0v = __ldg(ga.bias + gcol);
            const float b1v = __ldg(ga.bias + gcol + 1);
            #pragma unroll
            for (int h = 0; h < 2; h++) {
                float v0 = acc[mt][nt][h * 2 + 0] + b0v;
                float v1 = acc[mt][nt][h * 2 + 1] + b1v;
                const size_t ro = (size_t)(r_base + h * 8);
                if (EPI == 1) {
                    v0 = fmaxf(v0, 0.f);
                    v1 = fmaxf(v1, 0.f);
                    *reinterpret_cast<__half2*>(ga.Oh + ro * ldo + gcol) =
                        __floats2half2_rn(v0, v1);
                } else {
                    *reinterpret_cast<float2*>(ga.Y + ro * ldy + gcol) = make_float2(v0, v1);
                }
            }
        }
    }
}

// ---------------------------------------------------------------------------
struct LArgs {
    const float* resf;
    const float* Y;
    const float *g, *b;
    float* x1f;
    __half* x1h;
    float* outf;
    int coloff;
};

// MODE 0: x1 = LN(res + Y) -> x1f (fp32) + x1h (fp16)
// MODE 1: out[., coloff:+512] = LN(res + Y)
template<int MODE>
__global__ __launch_bounds__(256)
void ln_kernel(LArgs la0, LArgs la1, int ldout)
{
    const LArgs la = blockIdx.z ? la1 : la0;
    const int w = threadIdx.x >> 5, lane = threadIdx.x & 31;
    const size_t row = (size_t)blockIdx.x * 8 + w;
    const size_t rb = row * EDIM;

    float v[16];
    #pragma unroll
    for (int j = 0; j < 16; j++) {
        const int c = j * 32 + lane;
        v[j] = la.Y[rb + c] + la.resf[rb + c];
    }
    float s = 0.f;
    #pragma unroll
    for (int j = 0; j < 16; j++) s += v[j];
    #pragma unroll
    for (int o = 16; o > 0; o >>= 1) s += __shfl_xor_sync(0xffffffffu, s, o);
    const float mean = s * (1.0f / EDIM);
    float q = 0.f;
    #pragma unroll
    for (int j = 0; j < 16; j++) { const float d = v[j] - mean; q += d * d; }
    #pragma unroll
    for (int o = 16; o > 0; o >>= 1) q += __shfl_xor_sync(0xffffffffu, q, o);
    const float rs = rsqrtf(q * (1.0f / EDIM) + LN_EPS);

    #pragma unroll
    for (int j = 0; j < 16; j++) {
        const int c = j * 32 + lane;
        const float o = (v[j] - mean) * rs * la.g[c] + la.b[c];
        if (MODE == 0) {
            la.x1f[rb + c] = o;
            la.x1h[rb + c] = __float2half_rn(o);
        } else {
            la.outf[row * ldout + la.coloff + c] = o;
        }
    }
}

// ---------------------------------------------------------------------------
__global__ void conv_in_kernel(const float* __restrict__ src0, const float* __restrict__ src1,
                               __half* __restrict__ h, int n4)
{
    const int i = blockIdx.x * blockDim.x + threadIdx.x;
    if (i >= n4) return;
    const float* src = blockIdx.z ? src1 : src0;
    const size_t base = (size_t)blockIdx.z * n4;
    const float4 v = reinterpret_cast<const float4*>(src)[i];
    const size_t o = (base + i) * 4;
    reinterpret_cast<__half2*>(h + o)[0] = __floats2half2_rn(v.x, v.y);
    reinterpret_cast<__half2*>(h + o)[1] = __floats2half2_rn(v.z, v.w);
}

struct ConvSet { const float* src; __half* dst; };
__global__ void conv_w_kernel(ConvSet s0, ConvSet s1, ConvSet s2, ConvSet s3, int n4)
{
    const int i = blockIdx.x * blockDim.x + threadIdx.x;
    if (i >= n4) return;
    ConvSet ss = s0;
    if (blockIdx.y == 1) ss = s1;
    else if (blockIdx.y == 2) ss = s2;
    else if (blockIdx.y == 3) ss = s3;
    const float4 v = reinterpret_cast<const float4*>(ss.src)[i];
    const size_t o = (size_t)i * 4;
    reinterpret_cast<__half2*>(ss.dst + o)[0] = __floats2half2_rn(v.x, v.y);
    reinterpret_cast<__half2*>(ss.dst + o)[1] = __floats2half2_rn(v.z, v.w);
}

// ---------------------------------------------------------------------------
// Wvo = Wo @ Wv (512^3) -> fp16; blockIdx.x==16 slice computes bvo.
struct FuseArgs { const float *Wo, *Wv, *bv, *bo; __half* wh; float* bvo; };
__global__ void fuse_w_kernel(FuseArgs f0, FuseArgs f1)
{
    const FuseArgs f = blockIdx.z ? f1 : f0;
    const int tx = threadIdx.x, ty = threadIdx.y;
    const int j0 = blockIdx.y * 32;

    if (blockIdx.x == 16) {
        const int tid  = ty * 16 + tx;
        const int warp = tid >> 5, lane = tid & 31;
        const int row  = j0 + warp * 4 + (lane >> 3);
        const int sub  = lane & 7;
        float s = 0.f;
        for (int k = sub; k < 512; k += 8) s += f.Wo[row * 512 + k] * f.bv[k];
        #pragma unroll
        for (int o = 4; o > 0; o >>= 1) s += __shfl_xor_sync(0xffffffffu, s, o);
        if (sub == 0) f.bvo[row] = s + f.bo[row];
        return;
    }

    __shared__ float As[32][33];
    __shared__ float Bs[32][33];
    const int m0 = blockIdx.x * 32;
    float a00 = 0.f, a01 = 0.f, a10 = 0.f, a11 = 0.f;

    for (int k0 = 0; k0 < 512; k0 += 32) {
        for (int idx = ty * 16 + tx; idx < 1024; idx += 256) {
            const int r = idx >> 5, c = idx & 31;
            As[r][c] = f.Wo[(j0 + r) * 512 + k0 + c];
            Bs[r][c] = f.Wv[(k0 + r) * 512 + m0 + c];
        }
        __syncthreads();
        #pragma unroll
        for (int kk = 0; kk < 32; kk++) {
            const float x0 = As[ty][kk], x1 = As[ty + 16][kk];
            const float y0 = Bs[kk][tx], y1 = Bs[kk][tx + 16];
            a00 += x0 * y0; a01 += x0 * y1;
            a10 += x1 * y0; a11 += x1 * y1;
        }
        __syncthreads();
    }
    f.wh[(size_t)(j0 + ty)      * 512 + m0 + tx]      = __float2half_rn(a00);
    f.wh[(size_t)(j0 + ty)      * 512 + m0 + tx + 16] = __float2half_rn(a01);
    f.wh[(size_t)(j0 + ty + 16) * 512 + m0 + tx]      = __float2half_rn(a10);
    f.wh[(size_t)(j0 + ty + 16) * 512 + m0 + tx + 16] = __float2half_rn(a11);
}

// ---------------------------------------------------------------------------
extern "C" void kernel_launch(void* const* d_in, const int* in_sizes, int n_in,
                              void* d_out, int out_size)
{
    const float* dna = (const float*)d_in[0];
    const float* mol = (const float*)d_in[1];
    const float* in_w[2]  = {(const float*)d_in[2],  (const float*)d_in[6]};
    const float* in_b[2]  = {(const float*)d_in[3],  (const float*)d_in[7]};
    const float* out_w[2] = {(const float*)d_in[4],  (const float*)d_in[8]};
    const float* out_b[2] = {(const float*)d_in[5],  (const float*)d_in[9]};
    const float* lnA_g[2] = {(const float*)d_in[10], (const float*)d_in[12]};
    const float* lnA_b[2] = {(const float*)d_in[11], (const float*)d_in[13]};
    const float* lnC_g[2] = {(const float*)d_in[14], (const float*)d_in[16]};
    const float* lnC_b[2] = {(const float*)d_in[15], (const float*)d_in[17]};
    const float* w1[2] = {(const float*)d_in[18], (const float*)d_in[22]};
    const float* b1[2] = {(const float*)d_in[19], (const float*)d_in[23]};
    const float* w2[2] = {(const float*)d_in[20], (const float*)d_in[24]};
    const float* b2[2] = {(const float*)d_in[21], (const float*)d_in[25]};
    float* out = (float*)d_out;

    float *bvo, *Y, *x1f;
    __half *wh, *xh, *x1h, *hh;
    cudaGetSymbolAddress((void**)&bvo, g_bvo);
    cudaGetSymbolAddress((void**)&Y,   g_Y);
    cudaGetSymbolAddress((void**)&x1f, g_x1f);
    cudaGetSymbolAddress((void**)&wh,  g_wh);
    cudaGetSymbolAddress((void**)&xh,  g_xh);
    cudaGetSymbolAddress((void**)&x1h, g_x1h);
    cudaGetSymbolAddress((void**)&hh,  g_hh);

    cudaFuncSetAttribute(gemm_mma<0>, cudaFuncAttributeMaxDynamicSharedMemorySize, DYN_SMEM);
    cudaFuncSetAttribute(gemm_mma<1>, cudaFuncAttributeMaxDynamicSharedMemorySize, DYN_SMEM);

    // ---- prologue ----
    conv_in_kernel<<<dim3(MN / 4 / 256, 1, 2), 256>>>(dna, mol, xh, MN / 4);
    {
        ConvSet s0 = {w1[0], wh + 0 * WSTRIDE + WOFF_W1};
        ConvSet s1 = {w2[0], wh + 0 * WSTRIDE + WOFF_W2};
        ConvSet s2 = {w1[1], wh + 1 * WSTRIDE + WOFF_W1};
        ConvSet s3 = {w2[1], wh + 1 * WSTRIDE + WOFF_W2};
        conv_w_kernel<<<dim3(HDIM * EDIM / 4 / 256, 4), 256>>>(s0, s1, s2, s3, HDIM * EDIM / 4);
    }
    {
        FuseArgs f0 = {out_w[0], in_w[0] + 2 * EDIM * EDIM, in_b[0] + 2 * EDIM, out_b[0],
                       wh + 0 * WSTRIDE + WOFF_VO, bvo + 0 * EDIM};
        FuseArgs f1 = {out_w[1], in_w[1] + 2 * EDIM * EDIM, in_b[1] + 2 * EDIM, out_b[1],
                       wh + 1 * WSTRIDE + WOFF_VO, bvo + 1 * EDIM};
        fuse_w_kernel<<<dim3(17, 16, 2), dim3(16, 16)>>>(f0, f1);
    }

    // ---- main pipeline (both streams via blockIdx.z) ----
    // stream 0 (dna side) attends over mol (xh+MN); stream 1 over dna (xh+0)
    // gemm A -> Y
    {
        GArgs a0 = {xh + MN, wh + 0 * WSTRIDE + WOFF_VO, bvo + 0 * EDIM, Y + 0 * MN, nullptr};
        GArgs a1 = {xh,      wh + 1 * WSTRIDE + WOFF_VO, bvo + 1 * EDIM, Y + 1 * MN, nullptr};
        gemm_mma<0><<<dim3(EDIM / BN, MROWS / BM, 2), NTHR, DYN_SMEM>>>(
            a0, a1, EDIM, EDIM, EDIM, EDIM, 0);
    }
    // ln1 -> x1 (fp32 + fp16)
    {
        LArgs l0 = {dna, Y + 0 * MN, lnA_g[0], lnA_b[0], x1f,      x1h,      nullptr, 0};
        LArgs l1 = {mol, Y + 1 * MN, lnA_g[1], lnA_b[1], x1f + MN, x1h + MN, nullptr, 0};
        ln_kernel<0><<<dim3(MROWS / 8, 1, 2), 256>>>(l0, l1, 0);
    }
    // gemm B (FFN up + relu) -> H (fp16)
    {
        GArgs a0 = {x1h,      wh + 0 * WSTRIDE + WOFF_W1, b1[0], nullptr, hh};
        GArgs a1 = {x1h + MN, wh + 1 * WSTRIDE + WOFF_W1, b1[1], nullptr, hh + MH};
        gemm_mma<1><<<dim3(HDIM / BN, MROWS / BM, 2), NTHR, DYN_SMEM>>>(
            a0, a1, EDIM, EDIM, EDIM, 0, HDIM);
    }
    // gemm C (FFN down) -> Y
    {
        GArgs a0 = {hh,      wh + 0 * WSTRIDE + WOFF_W2, b2[0], Y + 0 * MN, nullptr};
        GArgs a1 = {hh + MH, wh + 1 * WSTRIDE + WOFF_W2, b2[1], Y + 1 * MN, nullptr};
        gemm_mma<0><<<dim3(EDIM / BN, MROWS / BM, 2), NTHR, DYN_SMEM>>>(
            a0, a1, HDIM, HDIM, HDIM, EDIM, 0);
    }
    // ln2 -> output halves
    {
        LArgs l0 = {x1f,      Y + 0 * MN, lnC_g[0], lnC_b[0], nullptr, nullptr, out, 0};
        LArgs l1 = {x1f + MN, Y + 1 * MN, lnC_g[1], lnC_b[1], nullptr, nullptr, out, EDIM};
        ln_kernel<1><<<dim3(MROWS / 8, 1, 2), 256>>>(l0, l1, 2 * EDIM);
    }
}

// round 11
// speedup vs baseline: 1.1300x; 1.1300x over previous
#include <cuda_runtime.h>
#include <cuda_fp16.h>
#include <cstdint>

#define EDIM   512
#define MROWS  32768
#define HDIM   1024
#define LN_EPS 1e-5f

// ---------------- mma.sync GEMM tiling (R9 config: best measured) ----------------
#define BM 128
#define BN 128
#define BK 64
#define NTHR 256

#define ROWB   144                   // 128B row + 16B pad: +4 banks/row, conflict-free ldmatrix
#define ARRB   (128 * ROWB)          // 18432
#define STAGEB (2 * ARRB)            // A, B -> 36864
#define NSTAGE 3
#define DYN_SMEM (NSTAGE * STAGEB)   // 110592  -> 2 CTAs/SM

#define MN (MROWS * EDIM)
#define MH (MROWS * HDIM)
#define WOFF_VO 0
#define WOFF_W1 262144
#define WOFF_W2 786432
#define WSTRIDE 1310720

// ---------------- device scratch ----------------
__device__ float   g_bvo[2 * EDIM];
__device__ __half  g_wh [2 * WSTRIDE];      // fp16 weights (B operands)
__device__ __half  g_xh [2 * MN];           // fp16 inputs
__device__ __half  g_x1h[2 * MN];           // fp16 x1 (GEMM operand + ln2 residual)
__device__ __half  g_hh [2l * MH];          // fp16 relu(FFN up)
__device__ __half  g_Yh [2 * MN];           // fp16 GEMM out scratch

// ---------------- PTX helpers ----------------
__device__ __forceinline__ uint32_t smem_u32(const void* p) {
    uint32_t a;
    asm("{ .reg .u64 t; cvta.to.shared.u64 t, %1; cvt.u32.u64 %0, t; }" : "=r"(a) : "l"(p));
    return a;
}
__device__ __forceinline__ void ldsm4(uint32_t* r, uint32_t addr) {
    asm volatile("ldmatrix.sync.aligned.x4.m8n8.shared.b16 {%0,%1,%2,%3}, [%4];"
                 : "=r"(r[0]), "=r"(r[1]), "=r"(r[2]), "=r"(r[3]) : "r"(addr));
}
__device__ __forceinline__ void mma_f16(float* c, const uint32_t* a, const uint32_t* b) {
    asm volatile(
        "mma.sync.aligned.m16n8k16.row.col.f32.f16.f16.f32 "
        "{%0,%1,%2,%3}, {%4,%5,%6,%7}, {%8,%9}, {%0,%1,%2,%3};"
        : "+f"(c[0]), "+f"(c[1]), "+f"(c[2]), "+f"(c[3])
        : "r"(a[0]), "r"(a[1]), "r"(a[2]), "r"(a[3]), "r"(b[0]), "r"(b[1]));
}
__device__ __forceinline__ void cp16(uint32_t dst, const void* src) {
    asm volatile("cp.async.cg.shared.global [%0], [%1], 16;" :: "r"(dst), "l"(src) : "memory");
}

// ---------------------------------------------------------------------------
struct GArgs {
    const __half *Ah, *Bh;
    const float* bias;
    __half* Oh;
};

// GEMM: C[row0:BM, ncol0:BN] = A @ B^T (K-major fp16, fp32 accum).
// Warp grid 2(M) x 4(N); warp tile 64x32.
// Oh = fp16(acc + bias), with relu if RELU.
template<int RELU>
__global__ __launch_bounds__(NTHR, 2)
void gemm_mma(GArgs ga0, GArgs ga1, int lda, int ldb, int K, int ldo)
{
    extern __shared__ char smraw[];
    const uint32_t sb = smem_u32(smraw);
    const GArgs ga = blockIdx.z ? ga1 : ga0;

    const int t  = threadIdx.x;
    const int l  = t & 31;
    const int w  = t >> 5;
    const int wr = w >> 2;               // 0..1 (M half)
    const int wn = w & 3;                // 0..3 (N quarter)
    const int ncol0 = blockIdx.x * BN;   // N fastest -> A tile L2 reuse
    const int row0  = blockIdx.y * BM;

    // cp.async plan: 8 x 16B per thread per stage (4 A rows + 4 B rows, stride 32)
    const int crow = t >> 3;             // 0..31
    const int cc16 = (t & 7) * 16;
    const __half* pA = ga.Ah + (size_t)(row0 + crow) * lda + (t & 7) * 8;
    const __half* pB = ga.Bh + (size_t)(ncol0 + crow) * ldb + (t & 7) * 8;
    const uint32_t dbase = (uint32_t)crow * ROWB + cc16;

    float acc[4][4][4];
    #pragma unroll
    for (int mt = 0; mt < 4; mt++)
        #pragma unroll
        for (int nt = 0; nt < 4; nt++)
            #pragma unroll
            for (int e = 0; e < 4; e++) acc[mt][nt][e] = 0.f;

    const int nch = K / BK;

    auto fill = [&](int stage, int kt) {
        const uint32_t dst = sb + stage * STAGEB;
        #pragma unroll
        for (int j = 0; j < 4; j++) {
            cp16(dst + dbase + (uint32_t)(j * 32) * ROWB,        pA + (size_t)(j * 32) * lda + kt);
            cp16(dst + ARRB + dbase + (uint32_t)(j * 32) * ROWB, pB + (size_t)(j * 32) * ldb + kt);
        }
    };

    fill(0, 0);
    asm volatile("cp.async.commit_group;" ::: "memory");
    fill(1, BK);
    asm volatile("cp.async.commit_group;" ::: "memory");

    const uint32_t a_row  = (uint32_t)(wr * 64 + (l & 15)) * ROWB;
    const uint32_t a_chk  = (uint32_t)(l >> 4) << 4;
    const uint32_t b_row0 = (uint32_t)(wn * 32 + (l >> 4) * 8 + (l & 7)) * ROWB;
    const uint32_t b_chk  = (uint32_t)((l >> 3) & 1) << 4;

    int st_cur = 0, st_n2 = 2;
    for (int ch = 0; ch < nch; ch++) {
        asm volatile("cp.async.wait_group 1;" ::: "memory");
        __syncthreads();

        if (ch + 2 < nch) fill(st_n2, (ch + 2) * BK);
        asm volatile("cp.async.commit_group;" ::: "memory");

        const uint32_t sA = sb + st_cur * STAGEB;
        #pragma unroll
        for (int ks = 0; ks < 4; ks++) {
            const uint32_t koff = (uint32_t)ks * 32;   // 16 halves per k-step
            uint32_t b_h[2][4];
            #pragma unroll
            for (int p = 0; p < 2; p++)
                ldsm4(b_h[p], sA + ARRB + b_row0 + (uint32_t)(p * 16) * ROWB + koff + b_chk);
            uint32_t a[4][4];
            #pragma unroll
            for (int mt = 0; mt < 4; mt++)
                ldsm4(a[mt], sA + a_row + (uint32_t)(mt * 16) * ROWB + koff + a_chk);
            #pragma unroll
            for (int mt = 0; mt < 4; mt++)
                #pragma unroll
                for (int nt = 0; nt < 4; nt++)
                    mma_f16(acc[mt][nt], a[mt], &b_h[nt >> 1][(nt & 1) * 2]);
        }
        st_cur = (st_cur == 2) ? 0 : st_cur + 1;
        st_n2  = (st_n2  == 2) ? 0 : st_n2  + 1;
    }

    // ---------------- epilogue: fp16 store ----------------
    #pragma unroll
    for (int mt = 0; mt < 4; mt++) {
        #pragma unroll
        for (int nt = 0; nt < 4; nt++) {
            const int r_base = row0 + wr * 64 + mt * 16 + (l >> 2);
            const int gcol   = ncol0 + wn * 32 + nt * 8 + (l & 3) * 2;
            const float b0v = __ldg(ga.bias + gcol);
            const float b1v = __ldg(ga.bias + gcol + 1);
            #pragma unroll
            for (int h = 0; h < 2; h++) {
                float v0 = acc[mt][nt][h * 2 + 0] + b0v;
                float v1 = acc[mt][nt][h * 2 + 1] + b1v;
                if (RELU) {
                    v0 = fmaxf(v0, 0.f);
                    v1 = fmaxf(v1, 0.f);
                }
                const size_t ro = (size_t)(r_base + h * 8);
                *reinterpret_cast<__half2*>(ga.Oh + ro * ldo + gcol) = __floats2half2_rn(v0, v1);
            }
        }
    }
}

// ---------------------------------------------------------------------------
struct LArgs {
    const float* resf;       // MODE 0 residual (fp32 original input)
    const __half* resh;      // MODE 1 residual (fp16 x1)
    const __half* Yh;        // GEMM output (fp16)
    const float *g, *b;
    __half* x1h;             // MODE 0 out
    float* outf;             // MODE 1 out
    int coloff;
};

// MODE 0: x1h = fp16(LN(resf + Yh))
// MODE 1: out[., coloff:+512] = LN(resh + Yh)
template<int MODE>
__global__ __launch_bounds__(256)
void ln_kernel(LArgs la0, LArgs la1, int ldout)
{
    const LArgs la = blockIdx.z ? la1 : la0;
    const int w = threadIdx.x >> 5, lane = threadIdx.x & 31;
    const size_t row = (size_t)blockIdx.x * 8 + w;
    const size_t rb = row * EDIM;

    float v[16];
    #pragma unroll
    for (int j = 0; j < 16; j++) {
        const int c = j * 32 + lane;
        const float r = (MODE == 0) ? la.resf[rb + c] : __half2float(la.resh[rb + c]);
        v[j] = __half2float(la.Yh[rb + c]) + r;
    }
    float s = 0.f;
    #pragma unroll
    for (int j = 0; j < 16; j++) s += v[j];
    #pragma unroll
    for (int o = 16; o > 0; o >>= 1) s += __shfl_xor_sync(0xffffffffu, s, o);
    const float mean = s * (1.0f / EDIM);
    float q = 0.f;
    #pragma unroll
    for (int j = 0; j < 16; j++) { const float d = v[j] - mean; q += d * d; }
    #pragma unroll
    for (int o = 16; o > 0; o >>= 1) q += __shfl_xor_sync(0xffffffffu, q, o);
    const float rs = rsqrtf(q * (1.0f / EDIM) + LN_EPS);

    #pragma unroll
    for (int j = 0; j < 16; j++) {
        const int c = j * 32 + lane;
        const float o = (v[j] - mean) * rs * la.g[c] + la.b[c];
        if (MODE == 0) la.x1h[rb + c] = __float2half_rn(o);
        else           la.outf[row * ldout + la.coloff + c] = o;
    }
}

// ---------------------------------------------------------------------------
__global__ void conv_in_kernel(const float* __restrict__ src0, const float* __restrict__ src1,
                               __half* __restrict__ h, int n4)
{
    const int i = blockIdx.x * blockDim.x + threadIdx.x;
    if (i >= n4) return;
    const float* src = blockIdx.z ? src1 : src0;
    const size_t base = (size_t)blockIdx.z * n4;
    const float4 v = reinterpret_cast<const float4*>(src)[i];
    const size_t o = (base + i) * 4;
    reinterpret_cast<__half2*>(h + o)[0] = __floats2half2_rn(v.x, v.y);
    reinterpret_cast<__half2*>(h + o)[1] = __floats2half2_rn(v.z, v.w);
}

struct ConvSet { const float* src; __half* dst; };
__global__ void conv_w_kernel(ConvSet s0, ConvSet s1, ConvSet s2, ConvSet s3, int n4)
{
    const int i = blockIdx.x * blockDim.x + threadIdx.x;
    if (i >= n4) return;
    ConvSet ss = s0;
    if (blockIdx.y == 1) ss = s1;
    else if (blockIdx.y == 2) ss = s2;
    else if (blockIdx.y == 3) ss = s3;
    const float4 v = reinterpret_cast<const float4*>(ss.src)[i];
    const size_t o = (size_t)i * 4;
    reinterpret_cast<__half2*>(ss.dst + o)[0] = __floats2half2_rn(v.x, v.y);
    reinterpret_cast<__half2*>(ss.dst + o)[1] = __floats2half2_rn(v.z, v.w);
}

// ---------------------------------------------------------------------------
// Wvo = Wo @ Wv (512^3) -> fp16; blockIdx.x==16 slice computes bvo.
struct FuseArgs { const float *Wo, *Wv, *bv, *bo; __half* wh; float* bvo; };
__global__ void fuse_w_kernel(FuseArgs f0, FuseArgs f1)
{
    const FuseArgs f = blockIdx.z ? f1 : f0;
    const int tx = threadIdx.x, ty = threadIdx.y;
    const int j0 = blockIdx.y * 32;

    if (blockIdx.x == 16) {
        const int tid  = ty * 16 + tx;
        const int warp = tid >> 5, lane = tid & 31;
        const int row  = j0 + warp * 4 + (lane >> 3);
        const int sub  = lane & 7;
        float s = 0.f;
        for (int k = sub; k < 512; k += 8) s += f.Wo[row * 512 + k] * f.bv[k];
        #pragma unroll
        for (int o = 4; o > 0; o >>= 1) s += __shfl_xor_sync(0xffffffffu, s, o);
        if (sub == 0) f.bvo[row] = s + f.bo[row];
        return;
    }

    __shared__ float As[32][33];
    __shared__ float Bs[32][33];
    const int m0 = blockIdx.x * 32;
    float a00 = 0.f, a01 = 0.f, a10 = 0.f, a11 = 0.f;

    for (int k0 = 0; k0 < 512; k0 += 32) {
        for (int idx = ty * 16 + tx; idx < 1024; idx += 256) {
            const int r = idx >> 5, c = idx & 31;
            As[r][c] = f.Wo[(j0 + r) * 512 + k0 + c];
            Bs[r][c] = f.Wv[(k0 + r) * 512 + m0 + c];
        }
        __syncthreads();
        #pragma unroll
        for (int kk = 0; kk < 32; kk++) {
            const float x0 = As[ty][kk], x1 = As[ty + 16][kk];
            const float y0 = Bs[kk][tx], y1 = Bs[kk][tx + 16];
            a00 += x0 * y0; a01 += x0 * y1;
            a10 += x1 * y0; a11 += x1 * y1;
        }
        __syncthreads();
    }
    f.wh[(size_t)(j0 + ty)      * 512 + m0 + tx]      = __float2half_rn(a00);
    f.wh[(size_t)(j0 + ty)      * 512 + m0 + tx + 16] = __float2half_rn(a01);
    f.wh[(size_t)(j0 + ty + 16) * 512 + m0 + tx]      = __float2half_rn(a10);
    f.wh[(size_t)(j0 + ty + 16) * 512 + m0 + tx + 16] = __float2half_rn(a11);
}

// ---------------------------------------------------------------------------
extern "C" void kernel_launch(void* const* d_in, const int* in_sizes, int n_in,
                              void* d_out, int out_size)
{
    const float* dna = (const float*)d_in[0];
    const float* mol = (const float*)d_in[1];
    const float* in_w[2]  = {(const float*)d_in[2],  (const float*)d_in[6]};
    const float* in_b[2]  = {(const float*)d_in[3],  (const float*)d_in[7]};
    const float* out_w[2] = {(const float*)d_in[4],  (const float*)d_in[8]};
    const float* out_b[2] = {(const float*)d_in[5],  (const float*)d_in[9]};
    const float* lnA_g[2] = {(const float*)d_in[10], (const float*)d_in[12]};
    const float* lnA_b[2] = {(const float*)d_in[11], (const float*)d_in[13]};
    const float* lnC_g[2] = {(const float*)d_in[14], (const float*)d_in[16]};
    const float* lnC_b[2] = {(const float*)d_in[15], (const float*)d_in[17]};
    const float* w1[2] = {(const float*)d_in[18], (const float*)d_in[22]};
    const float* b1[2] = {(const float*)d_in[19], (const float*)d_in[23]};
    const float* w2[2] = {(const float*)d_in[20], (const float*)d_in[24]};
    const float* b2[2] = {(const float*)d_in[21], (const float*)d_in[25]};
    float* out = (float*)d_out;

    float *bvo;
    __half *wh, *xh, *x1h, *hh, *Yh;
    cudaGetSymbolAddress((void**)&bvo, g_bvo);
    cudaGetSymbolAddress((void**)&Yh,  g_Yh);
    cudaGetSymbolAddress((void**)&wh,  g_wh);
    cudaGetSymbolAddress((void**)&xh,  g_xh);
    cudaGetSymbolAddress((void**)&x1h, g_x1h);
    cudaGetSymbolAddress((void**)&hh,  g_hh);

    cudaFuncSetAttribute(gemm_mma<0>, cudaFuncAttributeMaxDynamicSharedMemorySize, DYN_SMEM);
    cudaFuncSetAttribute(gemm_mma<1>, cudaFuncAttributeMaxDynamicSharedMemorySize, DYN_SMEM);

    // ---- prologue ----
    conv_in_kernel<<<dim3(MN / 4 / 256, 1, 2), 256>>>(dna, mol, xh, MN / 4);
    {
        ConvSet s0 = {w1[0], wh + 0 * WSTRIDE + WOFF_W1};
        ConvSet s1 = {w2[0], wh + 0 * WSTRIDE + WOFF_W2};
        ConvSet s2 = {w1[1], wh + 1 * WSTRIDE + WOFF_W1};
        ConvSet s3 = {w2[1], wh + 1 * WSTRIDE + WOFF_W2};
        conv_w_kernel<<<dim3(HDIM * EDIM / 4 / 256, 4), 256>>>(s0, s1, s2, s3, HDIM * EDIM / 4);
    }
    {
        FuseArgs f0 = {out_w[0], in_w[0] + 2 * EDIM * EDIM, in_b[0] + 2 * EDIM, out_b[0],
                       wh + 0 * WSTRIDE + WOFF_VO, bvo + 0 * EDIM};
        FuseArgs f1 = {out_w[1], in_w[1] + 2 * EDIM * EDIM, in_b[1] + 2 * EDIM, out_b[1],
                       wh + 1 * WSTRIDE + WOFF_VO, bvo + 1 * EDIM};
        fuse_w_kernel<<<dim3(17, 16, 2), dim3(16, 16)>>>(f0, f1);
    }

    // ---- main pipeline (both streams via blockIdx.z) ----
    // stream 0 (dna side) attends over mol (xh+MN); stream 1 over dna (xh+0)
    // gemm A -> Yh
    {
        GArgs a0 = {xh + MN, wh + 0 * WSTRIDE + WOFF_VO, bvo + 0 * EDIM, Yh + 0 * MN};
        GArgs a1 = {xh,      wh + 1 * WSTRIDE + WOFF_VO, bvo + 1 * EDIM, Yh + 1 * MN};
        gemm_mma<0><<<dim3(EDIM / BN, MROWS / BM, 2), NTHR, DYN_SMEM>>>(
            a0, a1, EDIM, EDIM, EDIM, EDIM);
    }
    // ln1 -> x1h
    {
        LArgs l0 = {dna, nullptr, Yh + 0 * MN, lnA_g[0], lnA_b[0], x1h,      nullptr, 0};
        LArgs l1 = {mol, nullptr, Yh + 1 * MN, lnA_g[1], lnA_b[1], x1h + MN, nullptr, 0};
        ln_kernel<0><<<dim3(MROWS / 8, 1, 2), 256>>>(l0, l1, 0);
    }
    // gemm B (FFN up + relu) -> hh
    {
        GArgs a0 = {x1h,      wh + 0 * WSTRIDE + WOFF_W1, b1[0], hh};
        GArgs a1 = {x1h + MN, wh + 1 * WSTRIDE + WOFF_W1, b1[1], hh + MH};
        gemm_mma<1><<<dim3(HDIM / BN, MROWS / BM, 2), NTHR, DYN_SMEM>>>(
            a0, a1, EDIM, EDIM, EDIM, HDIM);
    }
    // gemm C (FFN down) -> Yh
    {
        GArgs a0 = {hh,      wh + 0 * WSTRIDE + WOFF_W2, b2[0], Yh + 0 * MN};
        GArgs a1 = {hh + MH, wh + 1 * WSTRIDE + WOFF_W2, b2[1], Yh + 1 * MN};
        gemm_mma<0><<<dim3(EDIM / BN, MROWS / BM, 2), NTHR, DYN_SMEM>>>(
            a0, a1, HDIM, HDIM, HDIM, EDIM);
    }
    // ln2 -> output halves
    {
        LArgs l0 = {nullptr, x1h,      Yh + 0 * MN, lnC_g[0], lnC_b[0], nullptr, out, 0};
        LArgs l1 = {nullptr, x1h + MN, Yh + 1 * MN, lnC_g[1], lnC_b[1], nullptr, out, EDIM};
        ln_kernel<1><<<dim3(MROWS / 8, 1, 2), 256>>>(l0, l1, 2 * EDIM);
    }
}

// round 12
// speedup vs baseline: 1.2576x; 1.1130x over previous
#include <cuda_runtime.h>
#include <cuda_fp16.h>
#include <cstdint>

#define EDIM   512
#define MROWS  32768
#define HDIM   1024
#define LN_EPS 1e-5f

// ---------------- mma.sync GEMM tiling (R9/R11 config: best measured) ----------------
#define BM 128
#define BN 128
#define BK 64
#define NTHR 256

#define ROWB   144                   // 128B row + 16B pad: +4 banks/row, conflict-free ldmatrix
#define ARRB   (128 * ROWB)          // 18432
#define STAGEB (2 * ARRB)            // A, B -> 36864
#define NSTAGE 3
#define DYN_SMEM (NSTAGE * STAGEB)   // 110592  -> 2 CTAs/SM

#define MN (MROWS * EDIM)
#define MH (MROWS * HDIM)
#define WOFF_VO 0
#define WOFF_W1 262144
#define WOFF_W2 786432
#define WSTRIDE 1310720

// ---------------- device scratch ----------------
__device__ float   g_bvo[2 * EDIM];
__device__ float   g_zero[EDIM];            // zero bias for Wvo GEMM (static-zeroed)
__device__ __half  g_wh [2 * WSTRIDE];      // fp16 weights (B operands)
__device__ __half  g_woh[2 * EDIM * EDIM];  // fp16 Wo (A of Wvo GEMM)
__device__ __half  g_wvt[2 * EDIM * EDIM];  // fp16 Wv^T (B of Wvo GEMM)
__device__ __half  g_xh [2 * MN];           // fp16 inputs (GEMM-A operand + ln1 residual)
__device__ __half  g_x1h[2 * MN];           // fp16 x1 (GEMM operand + ln2 residual)
__device__ __half  g_hh [2l * MH];          // fp16 relu(FFN up)
__device__ __half  g_Yh [2 * MN];           // fp16 GEMM out scratch

// ---------------- PTX helpers ----------------
__device__ __forceinline__ uint32_t smem_u32(const void* p) {
    uint32_t a;
    asm("{ .reg .u64 t; cvta.to.shared.u64 t, %1; cvt.u32.u64 %0, t; }" : "=r"(a) : "l"(p));
    return a;
}
__device__ __forceinline__ void ldsm4(uint32_t* r, uint32_t addr) {
    asm volatile("ldmatrix.sync.aligned.x4.m8n8.shared.b16 {%0,%1,%2,%3}, [%4];"
                 : "=r"(r[0]), "=r"(r[1]), "=r"(r[2]), "=r"(r[3]) : "r"(addr));
}
__device__ __forceinline__ void mma_f16(float* c, const uint32_t* a, const uint32_t* b) {
    asm volatile(
        "mma.sync.aligned.m16n8k16.row.col.f32.f16.f16.f32 "
        "{%0,%1,%2,%3}, {%4,%5,%6,%7}, {%8,%9}, {%0,%1,%2,%3};"
        : "+f"(c[0]), "+f"(c[1]), "+f"(c[2]), "+f"(c[3])
        : "r"(a[0]), "r"(a[1]), "r"(a[2]), "r"(a[3]), "r"(b[0]), "r"(b[1]));
}
__device__ __forceinline__ void cp16(uint32_t dst, const void* src) {
    asm volatile("cp.async.cg.shared.global [%0], [%1], 16;" :: "r"(dst), "l"(src) : "memory");
}

// ---------------------------------------------------------------------------
struct GArgs {
    const __half *Ah, *Bh;
    const float* bias;
    __half* Oh;
};

// GEMM: C[row0:BM, ncol0:BN] = A @ B^T (K-major fp16, fp32 accum).
// Warp grid 2(M) x 4(N); warp tile 64x32.  Oh = fp16(acc + bias), relu if RELU.
template<int RELU>
__global__ __launch_bounds__(NTHR, 2)
void gemm_mma(GArgs ga0, GArgs ga1, int lda, int ldb, int K, int ldo)
{
    extern __shared__ char smraw[];
    const uint32_t sb = smem_u32(smraw);
    const GArgs ga = blockIdx.z ? ga1 : ga0;

    const int t  = threadIdx.x;
    const int l  = t & 31;
    const int w  = t >> 5;
    const int wr = w >> 2;
    const int wn = w & 3;
    const int ncol0 = blockIdx.x * BN;   // N fastest -> A tile L2 reuse
    const int row0  = blockIdx.y * BM;

    const int crow = t >> 3;
    const int cc16 = (t & 7) * 16;
    const __half* pA = ga.Ah + (size_t)(row0 + crow) * lda + (t & 7) * 8;
    const __half* pB = ga.Bh + (size_t)(ncol0 + crow) * ldb + (t & 7) * 8;
    const uint32_t dbase = (uint32_t)crow * ROWB + cc16;

    float acc[4][4][4];
    #pragma unroll
    for (int mt = 0; mt < 4; mt++)
        #pragma unroll
        for (int nt = 0; nt < 4; nt++)
            #pragma unroll
            for (int e = 0; e < 4; e++) acc[mt][nt][e] = 0.f;

    const int nch = K / BK;

    auto fill = [&](int stage, int kt) {
        const uint32_t dst = sb + stage * STAGEB;
        #pragma unroll
        for (int j = 0; j < 4; j++) {
            cp16(dst + dbase + (uint32_t)(j * 32) * ROWB,        pA + (size_t)(j * 32) * lda + kt);
            cp16(dst + ARRB + dbase + (uint32_t)(j * 32) * ROWB, pB + (size_t)(j * 32) * ldb + kt);
        }
    };

    fill(0, 0);
    asm volatile("cp.async.commit_group;" ::: "memory");
    fill(1, BK);
    asm volatile("cp.async.commit_group;" ::: "memory");

    const uint32_t a_row  = (uint32_t)(wr * 64 + (l & 15)) * ROWB;
    const uint32_t a_chk  = (uint32_t)(l >> 4) << 4;
    const uint32_t b_row0 = (uint32_t)(wn * 32 + (l >> 4) * 8 + (l & 7)) * ROWB;
    const uint32_t b_chk  = (uint32_t)((l >> 3) & 1) << 4;

    int st_cur = 0, st_n2 = 2;
    for (int ch = 0; ch < nch; ch++) {
        asm volatile("cp.async.wait_group 1;" ::: "memory");
        __syncthreads();

        if (ch + 2 < nch) fill(st_n2, (ch + 2) * BK);
        asm volatile("cp.async.commit_group;" ::: "memory");

        const uint32_t sA = sb + st_cur * STAGEB;
        #pragma unroll
        for (int ks = 0; ks < 4; ks++) {
            const uint32_t koff = (uint32_t)ks * 32;
            uint32_t b_h[2][4];
            #pragma unroll
            for (int p = 0; p < 2; p++)
                ldsm4(b_h[p], sA + ARRB + b_row0 + (uint32_t)(p * 16) * ROWB + koff + b_chk);
            uint32_t a[4][4];
            #pragma unroll
            for (int mt = 0; mt < 4; mt++)
                ldsm4(a[mt], sA + a_row + (uint32_t)(mt * 16) * ROWB + koff + a_chk);
            #pragma unroll
            for (int mt = 0; mt < 4; mt++)
                #pragma unroll
                for (int nt = 0; nt < 4; nt++)
                    mma_f16(acc[mt][nt], a[mt], &b_h[nt >> 1][(nt & 1) * 2]);
        }
        st_cur = (st_cur == 2) ? 0 : st_cur + 1;
        st_n2  = (st_n2  == 2) ? 0 : st_n2  + 1;
    }

    // epilogue: fp16 store
    #pragma unroll
    for (int mt = 0; mt < 4; mt++) {
        #pragma unroll
        for (int nt = 0; nt < 4; nt++) {
            const int r_base = row0 + wr * 64 + mt * 16 + (l >> 2);
            const int gcol   = ncol0 + wn * 32 + nt * 8 + (l & 3) * 2;
            const float b0v = __ldg(ga.bias + gcol);
            const float b1v = __ldg(ga.bias + gcol + 1);
            #pragma unroll
            for (int h = 0; h < 2; h++) {
                float v0 = acc[mt][nt][h * 2 + 0] + b0v;
                float v1 = acc[mt][nt][h * 2 + 1] + b1v;
                if (RELU) {
                    v0 = fmaxf(v0, 0.f);
                    v1 = fmaxf(v1, 0.f);
                }
                const size_t ro = (size_t)(r_base + h * 8);
                *reinterpret_cast<__half2*>(ga.Oh + ro * ldo + gcol) = __floats2half2_rn(v0, v1);
            }
        }
    }
}

// ---------------------------------------------------------------------------
struct LArgs {
    const __half* resh;      // residual (fp16)
    const __half* Yh;        // GEMM output (fp16)
    const float *g, *b;
    __half* x1h;             // MODE 0 out
    float* outf;             // MODE 1 out
    int coloff;
};

// Residual + LayerNorm, vectorized: lane owns 4 groups of 4 cols: c(g) = (l+32g)*4.
// MODE 0: x1h = fp16(LN(resh + Yh)).  MODE 1: out = LN(resh + Yh) (fp32).
template<int MODE>
__global__ __launch_bounds__(256)
void ln_kernel(LArgs la0, LArgs la1, int ldout)
{
    const LArgs la = blockIdx.z ? la1 : la0;
    const int w = threadIdx.x >> 5, lane = threadIdx.x & 31;
    const size_t row = (size_t)blockIdx.x * 8 + w;
    const size_t rb = row * EDIM;

    float v[16];
    #pragma unroll
    for (int g = 0; g < 4; g++) {
        const int c = (lane + 32 * g) * 4;
        const uint2 yv = *reinterpret_cast<const uint2*>(la.Yh + rb + c);
        const uint2 rv = *reinterpret_cast<const uint2*>(la.resh + rb + c);
        const float2 y0 = __half22float2(reinterpret_cast<const __half2*>(&yv)[0]);
        const float2 y1 = __half22float2(reinterpret_cast<const __half2*>(&yv)[1]);
        const float2 r0 = __half22float2(reinterpret_cast<const __half2*>(&rv)[0]);
        const float2 r1 = __half22float2(reinterpret_cast<const __half2*>(&rv)[1]);
        v[g * 4 + 0] = y0.x + r0.x;
        v[g * 4 + 1] = y0.y + r0.y;
        v[g * 4 + 2] = y1.x + r1.x;
        v[g * 4 + 3] = y1.y + r1.y;
    }
    float s = 0.f;
    #pragma unroll
    for (int j = 0; j < 16; j++) s += v[j];
    #pragma unroll
    for (int o = 16; o > 0; o >>= 1) s += __shfl_xor_sync(0xffffffffu, s, o);
    const float mean = s * (1.0f / EDIM);
    float q = 0.f;
    #pragma unroll
    for (int j = 0; j < 16; j++) { const float d = v[j] - mean; q += d * d; }
    #pragma unroll
    for (int o = 16; o > 0; o >>= 1) q += __shfl_xor_sync(0xffffffffu, q, o);
    const float rs = rsqrtf(q * (1.0f / EDIM) + LN_EPS);

    #pragma unroll
    for (int g = 0; g < 4; g++) {
        const int c = (lane + 32 * g) * 4;
        const float4 gg = *reinterpret_cast<const float4*>(la.g + c);
        const float4 bb = *reinterpret_cast<const float4*>(la.b + c);
        float o0 = (v[g * 4 + 0] - mean) * rs * gg.x + bb.x;
        float o1 = (v[g * 4 + 1] - mean) * rs * gg.y + bb.y;
        float o2 = (v[g * 4 + 2] - mean) * rs * gg.z + bb.z;
        float o3 = (v[g * 4 + 3] - mean) * rs * gg.w + bb.w;
        if (MODE == 0) {
            uint2 ov;
            reinterpret_cast<__half2*>(&ov)[0] = __floats2half2_rn(o0, o1);
            reinterpret_cast<__half2*>(&ov)[1] = __floats2half2_rn(o2, o3);
            *reinterpret_cast<uint2*>(la.x1h + rb + c) = ov;
        } else {
            *reinterpret_cast<float4*>(la.outf + row * ldout + la.coloff + c) =
                make_float4(o0, o1, o2, o3);
        }
    }
}

// ---------------------------------------------------------------------------
__global__ void conv_in_kernel(const float* __restrict__ src0, const float* __restrict__ src1,
                               __half* __restrict__ h, int n4)
{
    const int i = blockIdx.x * blockDim.x + threadIdx.x;
    if (i >= n4) return;
    const float* src = blockIdx.z ? src1 : src0;
    const size_t base = (size_t)blockIdx.z * n4;
    const float4 v = reinterpret_cast<const float4*>(src)[i];
    const size_t o = (base + i) * 4;
    reinterpret_cast<__half2*>(h + o)[0] = __floats2half2_rn(v.x, v.y);
    reinterpret_cast<__half2*>(h + o)[1] = __floats2half2_rn(v.z, v.w);
}

// fp32 -> fp16 convert; 6 matrices (w1/w2/Wo x 2 streams) via blockIdx.y
struct ConvSet { const float* src; __half* dst; int n4; };
__global__ void conv_w_kernel(ConvSet s0, ConvSet s1, ConvSet s2,
                              ConvSet s3, ConvSet s4, ConvSet s5)
{
    ConvSet ss = s0;
    if (blockIdx.y == 1) ss = s1;
    else if (blockIdx.y == 2) ss = s2;
    else if (blockIdx.y == 3) ss = s3;
    else if (blockIdx.y == 4) ss = s4;
    else if (blockIdx.y == 5) ss = s5;
    const int i = blockIdx.x * blockDim.x + threadIdx.x;
    if (i >= ss.n4) return;
    const float4 v = reinterpret_cast<const float4*>(ss.src)[i];
    const size_t o = (size_t)i * 4;
    reinterpret_cast<__half2*>(ss.dst + o)[0] = __floats2half2_rn(v.x, v.y);
    reinterpret_cast<__half2*>(ss.dst + o)[1] = __floats2half2_rn(v.z, v.w);
}

// ---------------------------------------------------------------------------
// Wv^T (fp16) + bvo.  grid (17, 16, 2), block (32, 32).
// x<16: transpose 32x32 tile of Wv.  x==16: bvo slice (first 256 threads).
struct TransArgs { const float *Wv, *Wo, *bv, *bo; __half* wvt; float* bvo; };
__global__ void trans_bvo_kernel(TransArgs t0, TransArgs t1)
{
    const TransArgs f = blockIdx.z ? t1 : t0;
    const int tx = threadIdx.x, ty = threadIdx.y;

    if (blockIdx.x == 16) {
        const int tid = ty * 32 + tx;
        if (tid < 256) {
            const int j0   = blockIdx.y * 32;
            const int warp = tid >> 5, lane = tid & 31;
            const int row  = j0 + warp * 4 + (lane >> 3);
            const int sub  = lane & 7;
            float s = 0.f;
            for (int k = sub; k < 512; k += 8) s += f.Wo[row * 512 + k] * f.bv[k];
            #pragma unroll
            for (int o = 4; o > 0; o >>= 1) s += __shfl_xor_sync(0xffffffffu, s, o);
            if (sub == 0) f.bvo[row] = s + f.bo[row];
        }
        return;
    }

    __shared__ float tile[32][33];
    const int k0 = blockIdx.y * 32;   // Wv row block
    const int m0 = blockIdx.x * 32;   // Wv col block
    tile[ty][tx] = f.Wv[(size_t)(k0 + ty) * 512 + m0 + tx];
    __syncthreads();
    // wvt[m, k] = Wv[k, m]
    f.wvt[(size_t)(m0 + ty) * 512 + k0 + tx] = __float2half_rn(tile[tx][ty]);
}

// ---------------------------------------------------------------------------
extern "C" void kernel_launch(void* const* d_in, const int* in_sizes, int n_in,
                              void* d_out, int out_size)
{
    const float* dna = (const float*)d_in[0];
    const float* mol = (const float*)d_in[1];
    const float* in_w[2]  = {(const float*)d_in[2],  (const float*)d_in[6]};
    const float* in_b[2]  = {(const float*)d_in[3],  (const float*)d_in[7]};
    const float* out_w[2] = {(const float*)d_in[4],  (const float*)d_in[8]};
    const float* out_b[2] = {(const float*)d_in[5],  (const float*)d_in[9]};
    const float* lnA_g[2] = {(const float*)d_in[10], (const float*)d_in[12]};
    const float* lnA_b[2] = {(const float*)d_in[11], (const float*)d_in[13]};
    const float* lnC_g[2] = {(const float*)d_in[14], (const float*)d_in[16]};
    const float* lnC_b[2] = {(const float*)d_in[15], (const float*)d_in[17]};
    const float* w1[2] = {(const float*)d_in[18], (const float*)d_in[22]};
    const float* b1[2] = {(const float*)d_in[19], (const float*)d_in[23]};
    const float* w2[2] = {(const float*)d_in[20], (const float*)d_in[24]};
    const float* b2[2] = {(const float*)d_in[21], (const float*)d_in[25]};
    float* out = (float*)d_out;

    float *bvo, *zero;
    __half *wh, *woh, *wvt, *xh, *x1h, *hh, *Yh;
    cudaGetSymbolAddress((void**)&bvo,  g_bvo);
    cudaGetSymbolAddress((void**)&zero, g_zero);
    cudaGetSymbolAddress((void**)&Yh,   g_Yh);
    cudaGetSymbolAddress((void**)&wh,   g_wh);
    cudaGetSymbolAddress((void**)&woh,  g_woh);
    cudaGetSymbolAddress((void**)&wvt,  g_wvt);
    cudaGetSymbolAddress((void**)&xh,   g_xh);
    cudaGetSymbolAddress((void**)&x1h,  g_x1h);
    cudaGetSymbolAddress((void**)&hh,   g_hh);

    cudaFuncSetAttribute(gemm_mma<0>, cudaFuncAttributeMaxDynamicSharedMemorySize, DYN_SMEM);
    cudaFuncSetAttribute(gemm_mma<1>, cudaFuncAttributeMaxDynamicSharedMemorySize, DYN_SMEM);

    // ---- prologue ----
    conv_in_kernel<<<dim3(MN / 4 / 256, 1, 2), 256>>>(dna, mol, xh, MN / 4);
    {
        const int nW = HDIM * EDIM / 4;      // 131072
        const int nO = EDIM * EDIM / 4;      // 65536
        ConvSet s0 = {w1[0],    wh + 0 * WSTRIDE + WOFF_W1, nW};
        ConvSet s1 = {w2[0],    wh + 0 * WSTRIDE + WOFF_W2, nW};
        ConvSet s2 = {w1[1],    wh + 1 * WSTRIDE + WOFF_W1, nW};
        ConvSet s3 = {w2[1],    wh + 1 * WSTRIDE + WOFF_W2, nW};
        ConvSet s4 = {out_w[0], woh,                        nO};
        ConvSet s5 = {out_w[1], woh + EDIM * EDIM,          nO};
        conv_w_kernel<<<dim3(nW / 256, 6), 256>>>(s0, s1, s2, s3, s4, s5);
    }
    {
        TransArgs t0 = {in_w[0] + 2 * EDIM * EDIM, out_w[0], in_b[0] + 2 * EDIM, out_b[0],
                        wvt,               bvo + 0 * EDIM};
        TransArgs t1 = {in_w[1] + 2 * EDIM * EDIM, out_w[1], in_b[1] + 2 * EDIM, out_b[1],
                        wvt + EDIM * EDIM, bvo + 1 * EDIM};
        trans_bvo_kernel<<<dim3(17, 16, 2), dim3(32, 32)>>>(t0, t1);
    }
    // Wvo = Wo @ Wv^T via tensor cores -> wh[VO] fp16
    {
        GArgs a0 = {woh,               wvt,               zero, wh + 0 * WSTRIDE + WOFF_VO};
        GArgs a1 = {woh + EDIM * EDIM, wvt + EDIM * EDIM, zero, wh + 1 * WSTRIDE + WOFF_VO};
        gemm_mma<0><<<dim3(EDIM / BN, EDIM / BM, 2), NTHR, DYN_SMEM>>>(
            a0, a1, EDIM, EDIM, EDIM, EDIM);
    }

    // ---- main pipeline (both streams via blockIdx.z) ----
    // stream 0 (dna side) attends over mol (xh+MN); stream 1 over dna (xh+0)
    // gemm A -> Yh
    {
        GArgs a0 = {xh + MN, wh + 0 * WSTRIDE + WOFF_VO, bvo + 0 * EDIM, Yh + 0 * MN};
        GArgs a1 = {xh,      wh + 1 * WSTRIDE + WOFF_VO, bvo + 1 * EDIM, Yh + 1 * MN};
        gemm_mma<0><<<dim3(EDIM / BN, MROWS / BM, 2), NTHR, DYN_SMEM>>>(
            a0, a1, EDIM, EDIM, EDIM, EDIM);
    }
    // ln1 -> x1h (residual = fp16 xh)
    {
        LArgs l0 = {xh,      Yh + 0 * MN, lnA_g[0], lnA_b[0], x1h,      nullptr, 0};
        LArgs l1 = {xh + MN, Yh + 1 * MN, lnA_g[1], lnA_b[1], x1h + MN, nullptr, 0};
        ln_kernel<0><<<dim3(MROWS / 8, 1, 2), 256>>>(l0, l1, 0);
    }
    // gemm B (FFN up + relu) -> hh
    {
        GArgs a0 = {x1h,      wh + 0 * WSTRIDE + WOFF_W1, b1[0], hh};
        GArgs a1 = {x1h + MN, wh + 1 * WSTRIDE + WOFF_W1, b1[1], hh + MH};
        gemm_mma<1><<<dim3(HDIM / BN, MROWS / BM, 2), NTHR, DYN_SMEM>>>(
            a0, a1, EDIM, EDIM, EDIM, HDIM);
    }
    // gemm C (FFN down) -> Yh
    {
        GArgs a0 = {hh,      wh + 0 * WSTRIDE + WOFF_W2, b2[0], Yh + 0 * MN};
        GArgs a1 = {hh + MH, wh + 1 * WSTRIDE + WOFF_W2, b2[1], Yh + 1 * MN};
        gemm_mma<0><<<dim3(EDIM / BN, MROWS / BM, 2), NTHR, DYN_SMEM>>>(
            a0, a1, HDIM, HDIM, HDIM, EDIM);
    }
    // ln2 -> output halves (residual = fp16 x1h)
    {
        LArgs l0 = {x1h,      Yh + 0 * MN, lnC_g[0], lnC_b[0], nullptr, out, 0};
        LArgs l1 = {x1h + MN, Yh + 1 * MN, lnC_g[1], lnC_b[1], nullptr, out, EDIM};
        ln_kernel<1><<<dim3(MROWS / 8, 1, 2), 256>>>(l0, l1, 2 * EDIM);
    }
}

// round 14
// speedup vs baseline: 1.2643x; 1.0053x over previous
#include <cuda_runtime.h>
#include <cuda_fp16.h>
#include <cstdint>

#define EDIM   512
#define MROWS  32768
#define HDIM   1024
#define LN_EPS 1e-5f

// ---------------- mma.sync GEMM tiling (best measured config) ----------------
#define BM 128
#define BN 128
#define BK 64
#define NTHR 256

#define ROWB   144                   // 128B row + 16B pad: +4 banks/row, conflict-free ldmatrix
#define ARRB   (128 * ROWB)          // 18432
#define STAGEB (2 * ARRB)            // A, B -> 36864
#define NSTAGE 3
#define DYN_SMEM (NSTAGE * STAGEB)   // 110592  -> 2 CTAs/SM

#define MN (MROWS * EDIM)
#define MH (MROWS * HDIM)
#define WOFF_VO 0
#define WOFF_W1 262144
#define WOFF_W2 786432
#define WSTRIDE 1310720

// ---------------- device scratch ----------------
__device__ float   g_bvo[2 * EDIM];
__device__ float   g_zero[EDIM];            // zero bias for Wvo GEMM (static-zeroed)
__device__ __half  g_wh [2 * WSTRIDE];      // fp16 weights (B operands)
__device__ __half  g_woh[2 * EDIM * EDIM];  // fp16 Wo (A of Wvo GEMM)
__device__ __half  g_wvt[2 * EDIM * EDIM];  // fp16 Wv^T (B of Wvo GEMM)
__device__ __half  g_xh [2 * MN];           // fp16 inputs (GEMM-A operand + ln1 residual)
__device__ __half  g_x1h[2 * MN];           // fp16 x1 (GEMM operand + ln2 residual)
__device__ __half  g_hh [2l * MH];          // fp16 relu(FFN up)
__device__ __half  g_Yh [2 * MN];           // fp16 GEMM out scratch

// ---------------- PTX helpers ----------------
__device__ __forceinline__ uint32_t smem_u32(const void* p) {
    uint32_t a;
    asm("{ .reg .u64 t; cvta.to.shared.u64 t, %1; cvt.u32.u64 %0, t; }" : "=r"(a) : "l"(p));
    return a;
}
__device__ __forceinline__ void ldsm4(uint32_t* r, uint32_t addr) {
    asm volatile("ldmatrix.sync.aligned.x4.m8n8.shared.b16 {%0,%1,%2,%3}, [%4];"
                 : "=r"(r[0]), "=r"(r[1]), "=r"(r[2]), "=r"(r[3]) : "r"(addr));
}
__device__ __forceinline__ void mma_f16(float* c, const uint32_t* a, const uint32_t* b) {
    asm volatile(
        "mma.sync.aligned.m16n8k16.row.col.f32.f16.f16.f32 "
        "{%0,%1,%2,%3}, {%4,%5,%6,%7}, {%8,%9}, {%0,%1,%2,%3};"
        : "+f"(c[0]), "+f"(c[1]), "+f"(c[2]), "+f"(c[3])
        : "r"(a[0]), "r"(a[1]), "r"(a[2]), "r"(a[3]), "r"(b[0]), "r"(b[1]));
}
__device__ __forceinline__ void cp16(uint32_t dst, const void* src) {
    asm volatile("cp.async.cg.shared.global [%0], [%1], 16;" :: "r"(dst), "l"(src) : "memory");
}

// ---------------------------------------------------------------------------
struct GArgs {
    const __half *Ah, *Bh;
    const float* bias;
    __half* Oh;
};

// GEMM: C[row0:BM, ncol0:BN] = A @ B^T (K-major fp16, fp32 accum).
// Warp grid 2(M) x 4(N); warp tile 64x32.  Oh = fp16(acc + bias), relu if RELU.
// Fill for chunk ch+2 is deferred past the first ks quarter so mma issue
// starts immediately after the barrier.
template<int RELU>
__global__ __launch_bounds__(NTHR, 2)
void gemm_mma(GArgs ga0, GArgs ga1, int lda, int ldb, int K, int ldo)
{
    extern __shared__ char smraw[];
    const uint32_t sb = smem_u32(smraw);
    const GArgs ga = blockIdx.z ? ga1 : ga0;

    const int t  = threadIdx.x;
    const int l  = t & 31;
    const int w  = t >> 5;
    const int wr = w >> 2;
    const int wn = w & 3;
    const int ncol0 = blockIdx.x * BN;   // N fastest -> A tile L2 reuse
    const int row0  = blockIdx.y * BM;

    const int crow = t >> 3;
    const int cc16 = (t & 7) * 16;
    const __half* pA = ga.Ah + (size_t)(row0 + crow) * lda + (t & 7) * 8;
    const __half* pB = ga.Bh + (size_t)(ncol0 + crow) * ldb + (t & 7) * 8;
    const uint32_t dbase = (uint32_t)crow * ROWB + cc16;

    float acc[4][4][4];
    #pragma unroll
    for (int mt = 0; mt < 4; mt++)
        #pragma unroll
        for (int nt = 0; nt < 4; nt++)
            #pragma unroll
            for (int e = 0; e < 4; e++) acc[mt][nt][e] = 0.f;

    const int nch = K / BK;

    auto fill = [&](int stage, int kt) {
        const uint32_t dst = sb + stage * STAGEB;
        #pragma unroll
        for (int j = 0; j < 4; j++) {
            cp16(dst + dbase + (uint32_t)(j * 32) * ROWB,        pA + (size_t)(j * 32) * lda + kt);
            cp16(dst + ARRB + dbase + (uint32_t)(j * 32) * ROWB, pB + (size_t)(j * 32) * ldb + kt);
        }
    };

    fill(0, 0);
    asm volatile("cp.async.commit_group;" ::: "memory");
    fill(1, BK);
    asm volatile("cp.async.commit_group;" ::: "memory");

    const uint32_t a_row  = (uint32_t)(wr * 64 + (l & 15)) * ROWB;
    const uint32_t a_chk  = (uint32_t)(l >> 4) << 4;
    const uint32_t b_row0 = (uint32_t)(wn * 32 + (l >> 4) * 8 + (l & 7)) * ROWB;
    const uint32_t b_chk  = (uint32_t)((l >> 3) & 1) << 4;

    auto compute_ks = [&](const uint32_t sA, int ks) {
        const uint32_t koff = (uint32_t)ks * 32;
        uint32_t b_h[2][4];
        #pragma unroll
        for (int p = 0; p < 2; p++)
            ldsm4(b_h[p], sA + ARRB + b_row0 + (uint32_t)(p * 16) * ROWB + koff + b_chk);
        uint32_t a[4][4];
        #pragma unroll
        for (int mt = 0; mt < 4; mt++)
            ldsm4(a[mt], sA + a_row + (uint32_t)(mt * 16) * ROWB + koff + a_chk);
        #pragma unroll
        for (int mt = 0; mt < 4; mt++)
            #pragma unroll
            for (int nt = 0; nt < 4; nt++)
                mma_f16(acc[mt][nt], a[mt], &b_h[nt >> 1][(nt & 1) * 2]);
    };

    int st_cur = 0, st_n2 = 2;
    for (int ch = 0; ch < nch; ch++) {
        asm volatile("cp.async.wait_group 1;" ::: "memory");
        __syncthreads();

        const uint32_t sA = sb + st_cur * STAGEB;
        compute_ks(sA, 0);                       // mma starts right after barrier

        if (ch + 2 < nch) fill(st_n2, (ch + 2) * BK);
        asm volatile("cp.async.commit_group;" ::: "memory");

        #pragma unroll
        for (int ks = 1; ks < 4; ks++) compute_ks(sA, ks);

        st_cur = (st_cur == 2) ? 0 : st_cur + 1;
        st_n2  = (st_n2  == 2) ? 0 : st_n2  + 1;
    }

    // epilogue: fp16 store
    #pragma unroll
    for (int mt = 0; mt < 4; mt++) {
        #pragma unroll
        for (int nt = 0; nt < 4; nt++) {
            const int r_base = row0 + wr * 64 + mt * 16 + (l >> 2);
            const int gcol   = ncol0 + wn * 32 + nt * 8 + (l & 3) * 2;
            const float b0v = __ldg(ga.bias + gcol);
            const float b1v = __ldg(ga.bias + gcol + 1);
            #pragma unroll
            for (int h = 0; h < 2; h++) {
                float v0 = acc[mt][nt][h * 2 + 0] + b0v;
                float v1 = acc[mt][nt][h * 2 + 1] + b1v;
                if (RELU) {
                    v0 = fmaxf(v0, 0.f);
                    v1 = fmaxf(v1, 0.f);
                }
                const size_t ro = (size_t)(r_base + h * 8);
                *reinterpret_cast<__half2*>(ga.Oh + ro * ldo + gcol) = __floats2half2_rn(v0, v1);
            }
        }
    }
}

// ---------------------------------------------------------------------------
struct LArgs {
    const __half* resh;      // residual (fp16)
    const __half* Yh;        // GEMM output (fp16)
    const float *g, *b;
    __half* x1h;             // MODE 0 out
    float* outf;             // MODE 1 out
    int coloff;
};

// Residual + LayerNorm, vectorized: lane owns 4 groups of 4 cols: c(g) = (l+32g)*4.
// MODE 0: x1h = fp16(LN(resh + Yh)).  MODE 1: out = LN(resh + Yh) (fp32).
template<int MODE>
__global__ __launch_bounds__(256)
void ln_kernel(LArgs la0, LArgs la1, int ldout)
{
    const LArgs la = blockIdx.z ? la1 : la0;
    const int w = threadIdx.x >> 5, lane = threadIdx.x & 31;
    const size_t row = (size_t)blockIdx.x * 8 + w;
    const size_t rb = row * EDIM;

    float v[16];
    #pragma unroll
    for (int g = 0; g < 4; g++) {
        const int c = (lane + 32 * g) * 4;
        const uint2 yv = *reinterpret_cast<const uint2*>(la.Yh + rb + c);
        const uint2 rv = *reinterpret_cast<const uint2*>(la.resh + rb + c);
        const float2 y0 = __half22float2(reinterpret_cast<const __half2*>(&yv)[0]);
        const float2 y1 = __half22float2(reinterpret_cast<const __half2*>(&yv)[1]);
        const float2 r0 = __half22float2(reinterpret_cast<const __half2*>(&rv)[0]);
        const float2 r1 = __half22float2(reinterpret_cast<const __half2*>(&rv)[1]);
        v[g * 4 + 0] = y0.x + r0.x;
        v[g * 4 + 1] = y0.y + r0.y;
        v[g * 4 + 2] = y1.x + r1.x;
        v[g * 4 + 3] = y1.y + r1.y;
    }
    float s = 0.f;
    #pragma unroll
    for (int j = 0; j < 16; j++) s += v[j];
    #pragma unroll
    for (int o = 16; o > 0; o >>= 1) s += __shfl_xor_sync(0xffffffffu, s, o);
    const float mean = s * (1.0f / EDIM);
    float q = 0.f;
    #pragma unroll
    for (int j = 0; j < 16; j++) { const float d = v[j] - mean; q += d * d; }
    #pragma unroll
    for (int o = 16; o > 0; o >>= 1) q += __shfl_xor_sync(0xffffffffu, q, o);
    const float rs = rsqrtf(q * (1.0f / EDIM) + LN_EPS);

    #pragma unroll
    for (int g = 0; g < 4; g++) {
        const int c = (lane + 32 * g) * 4;
        const float4 gg = *reinterpret_cast<const float4*>(la.g + c);
        const float4 bb = *reinterpret_cast<const float4*>(la.b + c);
        float o0 = (v[g * 4 + 0] - mean) * rs * gg.x + bb.x;
        float o1 = (v[g * 4 + 1] - mean) * rs * gg.y + bb.y;
        float o2 = (v[g * 4 + 2] - mean) * rs * gg.z + bb.z;
        float o3 = (v[g * 4 + 3] - mean) * rs * gg.w + bb.w;
        if (MODE == 0) {
            uint2 ov;
            reinterpret_cast<__half2*>(&ov)[0] = __floats2half2_rn(o0, o1);
            reinterpret_cast<__half2*>(&ov)[1] = __floats2half2_rn(o2, o3);
            *reinterpret_cast<uint2*>(la.x1h + rb + c) = ov;
        } else {
            *reinterpret_cast<float4*>(la.outf + row * ldout + la.coloff + c) =
                make_float4(o0, o1, o2, o3);
        }
    }
}

// ---------------------------------------------------------------------------
__global__ void conv_in_kernel(const float* __restrict__ src0, const float* __restrict__ src1,
                               __half* __restrict__ h, int n4)
{
    const int i = blockIdx.x * blockDim.x + threadIdx.x;
    if (i >= n4) return;
    const float* src = blockIdx.z ? src1 : src0;
    const size_t base = (size_t)blockIdx.z * n4;
    const float4 v = reinterpret_cast<const float4*>(src)[i];
    const size_t o = (base + i) * 4;
    reinterpret_cast<__half2*>(h + o)[0] = __floats2half2_rn(v.x, v.y);
    reinterpret_cast<__half2*>(h + o)[1] = __floats2half2_rn(v.z, v.w);
}

// fp32 -> fp16 convert; 6 matrices (w1/w2/Wo x 2 streams) via blockIdx.y
struct ConvSet { const float* src; __half* dst; int n4; };
__global__ void conv_w_kernel(ConvSet s0, ConvSet s1, ConvSet s2,
                              ConvSet s3, ConvSet s4, ConvSet s5)
{
    ConvSet ss = s0;
    if (blockIdx.y == 1) ss = s1;
    else if (blockIdx.y == 2) ss = s2;
    else if (blockIdx.y == 3) ss = s3;
    else if (blockIdx.y == 4) ss = s4;
    else if (blockIdx.y == 5) ss = s5;
    const int i = blockIdx.x * blockDim.x + threadIdx.x;
    if (i >= ss.n4) return;
    const float4 v = reinterpret_cast<const float4*>(ss.src)[i];
    const size_t o = (size_t)i * 4;
    reinterpret_cast<__half2*>(ss.dst + o)[0] = __floats2half2_rn(v.x, v.y);
    reinterpret_cast<__half2*>(ss.dst + o)[1] = __floats2half2_rn(v.z, v.w);
}

// ---------------------------------------------------------------------------
// Wv^T (fp16) + bvo.  grid (17, 16, 2), block (32, 32).
struct TransArgs { const float *Wv, *Wo, *bv, *bo; __half* wvt; float* bvo; };
__global__ void trans_bvo_kernel(TransArgs t0, TransArgs t1)
{
    const TransArgs f = blockIdx.z ? t1 : t0;
    const int tx = threadIdx.x, ty = threadIdx.y;

    if (blockIdx.x == 16) {
        const int tid = ty * 32 + tx;
        if (tid < 256) {
            const int j0   = blockIdx.y * 32;
            const int warp = tid >> 5, lane = tid & 31;
            const int row  = j0 + warp * 4 + (lane >> 3);
            const int sub  = lane & 7;
            float s = 0.f;
            for (int k = sub; k < 512; k += 8) s += f.Wo[row * 512 + k] * f.bv[k];
            #pragma unroll
            for (int o = 4; o > 0; o >>= 1) s += __shfl_xor_sync(0xffffffffu, s, o);
            if (sub == 0) f.bvo[row] = s + f.bo[row];
        }
        return;
    }

    __shared__ float tile[32][33];
    const int k0 = blockIdx.y * 32;
    const int m0 = blockIdx.x * 32;
    tile[ty][tx] = f.Wv[(size_t)(k0 + ty) * 512 + m0 + tx];
    __syncthreads();
    f.wvt[(size_t)(m0 + ty) * 512 + k0 + tx] = __float2half_rn(tile[tx][ty]);
}

// ---------------------------------------------------------------------------
extern "C" void kernel_launch(void* const* d_in, const int* in_sizes, int n_in,
                              void* d_out, int out_size)
{
    const float* dna = (const float*)d_in[0];
    const float* mol = (const float*)d_in[1];
    const float* in_w[2]  = {(const float*)d_in[2],  (const float*)d_in[6]};
    const float* in_b[2]  = {(const float*)d_in[3],  (const float*)d_in[7]};
    const float* out_w[2] = {(const float*)d_in[4],  (const float*)d_in[8]};
    const float* out_b[2] = {(const float*)d_in[5],  (const float*)d_in[9]};
    const float* lnA_g[2] = {(const float*)d_in[10], (const float*)d_in[12]};
    const float* lnA_b[2] = {(const float*)d_in[11], (const float*)d_in[13]};
    const float* lnC_g[2] = {(const float*)d_in[14], (const float*)d_in[16]};
    const float* lnC_b[2] = {(const float*)d_in[15], (const float*)d_in[17]};
    const float* w1[2] = {(const float*)d_in[18], (const float*)d_in[22]};
    const float* b1[2] = {(const float*)d_in[19], (const float*)d_in[23]};
    const float* w2[2] = {(const float*)d_in[20], (const float*)d_in[24]};
    const float* b2[2] = {(const float*)d_in[21], (const float*)d_in[25]};
    float* out = (float*)d_out;

    float *bvo, *zero;
    __half *wh, *woh, *wvt, *xh, *x1h, *hh, *Yh;
    cudaGetSymbolAddress((void**)&bvo,  g_bvo);
    cudaGetSymbolAddress((void**)&zero, g_zero);
    cudaGetSymbolAddress((void**)&Yh,   g_Yh);
    cudaGetSymbolAddress((void**)&wh,   g_wh);
    cudaGetSymbolAddress((void**)&woh,  g_woh);
    cudaGetSymbolAddress((void**)&wvt,  g_wvt);
    cudaGetSymbolAddress((void**)&xh,   g_xh);
    cudaGetSymbolAddress((void**)&x1h,  g_x1h);
    cudaGetSymbolAddress((void**)&hh,   g_hh);

    cudaFuncSetAttribute(gemm_mma<0>, cudaFuncAttributeMaxDynamicSharedMemorySize, DYN_SMEM);
    cudaFuncSetAttribute(gemm_mma<1>, cudaFuncAttributeMaxDynamicSharedMemorySize, DYN_SMEM);

    // Side stream + fork/join events, created once on the (uncaptured)
    // correctness call; captured graph topology is identical every capture.
    static cudaStream_t s2 = nullptr;
    static cudaEvent_t evFork = nullptr, evJoin = nullptr;
    if (s2 == nullptr) {
        cudaStreamCreateWithFlags(&s2, cudaStreamNonBlocking);
        cudaEventCreateWithFlags(&evFork, cudaEventDisableTiming);
        cudaEventCreateWithFlags(&evJoin, cudaEventDisableTiming);
    }

    // ---- prologue: weight path on s2, input conversion on main stream ----
    cudaEventRecord(evFork, 0);
    cudaStreamWaitEvent(s2, evFork, 0);

    {   // s2: weight converts -> Wv^T/bvo -> Wvo GEMM   (~18 us)
        const int nW = HDIM * EDIM / 4;
        const int nO = EDIM * EDIM / 4;
        ConvSet c0 = {w1[0],    wh + 0 * WSTRIDE + WOFF_W1, nW};
        ConvSet c1 = {w2[0],    wh + 0 * WSTRIDE + WOFF_W2, nW};
        ConvSet c2 = {w1[1],    wh + 1 * WSTRIDE + WOFF_W1, nW};
        ConvSet c3 = {w2[1],    wh + 1 * WSTRIDE + WOFF_W2, nW};
        ConvSet c4 = {out_w[0], woh,                        nO};
        ConvSet c5 = {out_w[1], woh + EDIM * EDIM,          nO};
        conv_w_kernel<<<dim3(nW / 256, 6), 256, 0, s2>>>(c0, c1, c2, c3, c4, c5);

        TransArgs t0 = {in_w[0] + 2 * EDIM * EDIM, out_w[0], in_b[0] + 2 * EDIM, out_b[0],
                        wvt,               bvo + 0 * EDIM};
        TransArgs t1 = {in_w[1] + 2 * EDIM * EDIM, out_w[1], in_b[1] + 2 * EDIM, out_b[1],
                        wvt + EDIM * EDIM, bvo + 1 * EDIM};
        trans_bvo_kernel<<<dim3(17, 16, 2), dim3(32, 32), 0, s2>>>(t0, t1);

        GArgs a0 = {woh,               wvt,               zero, wh + 0 * WSTRIDE + WOFF_VO};
        GArgs a1 = {woh + EDIM * EDIM, wvt + EDIM * EDIM, zero, wh + 1 * WSTRIDE + WOFF_VO};
        gemm_mma<0><<<dim3(EDIM / BN, EDIM / BM, 2), NTHR, DYN_SMEM, s2>>>(
            a0, a1, EDIM, EDIM, EDIM, EDIM);
        cudaEventRecord(evJoin, s2);
    }

    // main stream: input fp16 conversion (~28 us), concurrent with s2
    conv_in_kernel<<<dim3(MN / 4 / 256, 1, 2), 256>>>(dna, mol, xh, MN / 4);

    cudaStreamWaitEvent(0, evJoin, 0);   // join: gemmA needs Wvo + xh

    // ---- main pipeline (both streams of the problem via blockIdx.z) ----
    // stream 0 (dna side) attends over mol (xh+MN); stream 1 over dna (xh+0)
    // gemm A -> Yh
    {
        GArgs a0 = {xh + MN, wh + 0 * WSTRIDE + WOFF_VO, bvo + 0 * EDIM, Yh + 0 * MN};
        GArgs a1 = {xh,      wh + 1 * WSTRIDE + WOFF_VO, bvo + 1 * EDIM, Yh + 1 * MN};
        gemm_mma<0><<<dim3(EDIM / BN, MROWS / BM, 2), NTHR, DYN_SMEM>>>(
            a0, a1, EDIM, EDIM, EDIM, EDIM);
    }
    // ln1 -> x1h (residual = fp16 xh)
    {
        LArgs l0 = {xh,      Yh + 0 * MN, lnA_g[0], lnA_b[0], x1h,      nullptr, 0};
        LArgs l1 = {xh + MN, Yh + 1 * MN, lnA_g[1], lnA_b[1], x1h + MN, nullptr, 0};
        ln_kernel<0><<<dim3(MROWS / 8, 1, 2), 256>>>(l0, l1, 0);
    }
    // gemm B (FFN up + relu) -> hh
    {
        GArgs a0 = {x1h,      wh + 0 * WSTRIDE + WOFF_W1, b1[0], hh};
        GArgs a1 = {x1h + MN, wh + 1 * WSTRIDE + WOFF_W1, b1[1], hh + MH};
        gemm_mma<1><<<dim3(HDIM / BN, MROWS / BM, 2), NTHR, DYN_SMEM>>>(
            a0, a1, EDIM, EDIM, EDIM, HDIM);
    }
    // gemm C (FFN down) -> Yh
    {
        GArgs a0 = {hh,      wh + 0 * WSTRIDE + WOFF_W2, b2[0], Yh + 0 * MN};
        GArgs a1 = {hh + MH, wh + 1 * WSTRIDE + WOFF_W2, b2[1], Yh + 1 * MN};
        gemm_mma<0><<<dim3(EDIM / BN, MROWS / BM, 2), NTHR, DYN_SMEM>>>(
            a0, a1, HDIM, HDIM, HDIM, EDIM);
    }
    // ln2 -> output halves (residual = fp16 x1h)
    {
        LArgs l0 = {x1h,      Yh + 0 * MN, lnC_g[0], lnC_b[0], nullptr, out, 0};
        LArgs l1 = {x1h + MN, Yh + 1 * MN, lnC_g[1], lnC_b[1], nullptr, out, EDIM};
        ln_kernel<1><<<dim3(MROWS / 8, 1, 2), 256>>>(l0, l1, 2 * EDIM);
    }
}